// round 17
// baseline (speedup 1.0000x reference)
#include <cuda_runtime.h>
#include <cuda_bf16.h>

#define BB 16
#define CC 256
#define NPIX 4096
typedef __nv_bfloat16 bf16;
typedef unsigned int u32;
typedef unsigned short u16;

// ---------------- scratch (device globals) ----------------
__device__ float g_G[BB * CC * CC];
__device__ float g_Gp[3 * BB * CC * CC];
__device__ float g_T[BB * CC * CC];
__device__ float g_L[BB * CC * CC];
__device__ float g_Wvt[CC * CC];
__device__ float g_sxp[BB * CC * 64];
__device__ float g_sx[BB * CC], g_qs[BB * CC], g_ks[BB * CC], g_cv[BB * CC];
__device__ __align__(16) bf16 g_yh[(size_t)BB * CC * NPIX];
__device__ __align__(16) bf16 g_yl[(size_t)BB * CC * NPIX];
__device__ __align__(16) bf16 g_Mh[BB * CC * CC];
__device__ __align__(16) bf16 g_Ml[BB * CC * CC];

// ---------------- helpers ----------------
__device__ __forceinline__ void split2(float f, bf16& h, bf16& l) {
    h = __float2bfloat16(f);
    l = __float2bfloat16(f - __bfloat162float(h));
}
__device__ __forceinline__ u32 pack2(bf16 a, bf16 b) {
    return (u32)__bfloat16_as_ushort(a) | ((u32)__bfloat16_as_ushort(b) << 16);
}
__device__ __forceinline__ void cvt4(float4 v, uint2& h, uint2& l) {
    bf16 h0, l0, h1, l1, h2, l2, h3, l3;
    split2(v.x, h0, l0); split2(v.y, h1, l1);
    split2(v.z, h2, l2); split2(v.w, h3, l3);
    h = make_uint2(pack2(h0, h1), pack2(h2, h3));
    l = make_uint2(pack2(l0, l1), pack2(l2, l3));
}
__device__ __forceinline__ void mma16816(float* c, const u32* a, const u32* b) {
    asm volatile(
        "mma.sync.aligned.m16n8k16.row.col.f32.bf16.bf16.f32 "
        "{%0,%1,%2,%3}, {%4,%5,%6,%7}, {%8,%9}, {%0,%1,%2,%3};"
        : "+f"(c[0]), "+f"(c[1]), "+f"(c[2]), "+f"(c[3])
        : "r"(a[0]), "r"(a[1]), "r"(a[2]), "r"(a[3]), "r"(b[0]), "r"(b[1]));
}
__device__ __forceinline__ void cp16(u32 saddr, const void* g) {
    asm volatile("cp.async.ca.shared.global [%0], [%1], 16;" :: "r"(saddr), "l"(g));
}
__device__ __forceinline__ float b2f(u16 v) {
    return __bfloat162float(__ushort_as_bfloat16(v));
}
__device__ __forceinline__ void ldmx4t(u32* r, u32 saddr) {
    asm volatile(
        "ldmatrix.sync.aligned.m8n8.x4.trans.shared.b16 {%0,%1,%2,%3}, [%4];"
        : "=r"(r[0]), "=r"(r[1]), "=r"(r[2]), "=r"(r[3]) : "r"(saddr));
}
__device__ __forceinline__ void ldmx4(u32* r, u32 saddr) {
    asm volatile(
        "ldmatrix.sync.aligned.m8n8.x4.shared.b16 {%0,%1,%2,%3}, [%4];"
        : "=r"(r[0]), "=r"(r[1]), "=r"(r[2]), "=r"(r[3]) : "r"(saddr));
}

// ---------------- G GEMM: 2-stage cp.async, symmetric triangle schedule -----
// Stage layout (bytes from stage start): Ah[0,10240) Al[10240,20480)
//                                        Bh[20480,30720) Bl[30720,40960)
#define STGU_G 20480  // u16 per stage
__global__ void __launch_bounds__(256, 1) ggemm(
    const bf16* __restrict__ Ahg, const bf16* __restrict__ Alg,
    float* __restrict__ C)
{
    extern __shared__ __align__(16) u16 smp[];
    int tid = threadIdx.x, lane = tid & 31, wid = tid >> 5;
    int wm = wid >> 2, wn = wid & 3;
    int t0 = blockIdx.x;
    int by = (t0 + 1) >> 1, bx = t0 >> 1;        // {0:(0,0),1:(1,0),2:(1,1)}
    int kc2 = blockIdx.y;
    int b = blockIdx.z;
    int kbase = kc2 * 1376;
    int Titer = (kc2 == 2) ? 42 : 43;
    int zout = kc2 * 16 + b;
    bool diag = (bx == by);

    const bf16* Abh = Ahg + (size_t)b * CC * NPIX + (size_t)(by * 128) * NPIX + kbase;
    const bf16* Abl = Alg + (size_t)b * CC * NPIX + (size_t)(by * 128) * NPIX + kbase;
    const bf16* Bbh = Ahg + (size_t)b * CC * NPIX + (size_t)(bx * 128) * NPIX + kbase;
    const bf16* Bbl = Alg + (size_t)b * CC * NPIX + (size_t)(bx * 128) * NPIX + kbase;

    u32 sbase;
    asm("{ .reg .u64 t; cvta.to.shared.u64 t, %1; cvt.u32.u64 %0, t; }"
        : "=r"(sbase) : "l"(smp));

    auto PREF = [&](int t) {
        if (t < Titer) {
            int k0 = t * 32, st = t & 1;
            u32 s0 = sbase + (u32)(st * STGU_G) * 2;
#pragma unroll
            for (int j = 0; j < 2; j++) {
                int idx = tid * 2 + j;
                int rA = idx >> 2, cA8 = (idx & 3) * 8;
                u32 offA = (u32)(rA * 40 + cA8) * 2;
                cp16(s0 + offA,         Abh + (size_t)rA * NPIX + k0 + cA8);
                cp16(s0 + offA + 10240, Abl + (size_t)rA * NPIX + k0 + cA8);
                if (!diag) {
                    cp16(s0 + offA + 20480, Bbh + (size_t)rA * NPIX + k0 + cA8);
                    cp16(s0 + offA + 30720, Bbl + (size_t)rA * NPIX + k0 + cA8);
                }
            }
        }
        asm volatile("cp.async.commit_group;" ::: "memory");
    };

    float acc[4][4][4] = {};
    PREF(0);
    for (int t = 0; t < Titer; t++) {
        PREF(t + 1);
        asm volatile("cp.async.wait_group 1;" ::: "memory");
        __syncthreads();
        int st = t & 1;
        u32 stg2 = sbase + (u32)(st * STGU_G) * 2;
        int lrow = lane & 7, lm = lane >> 3;
        u32 bofs = diag ? 0u : 20480u;   // FIX: Bh tile starts at byte 20480
        u32 dlo  = 10240u;               // (B)l is +10240 bytes from (B)h
#pragma unroll
        for (int kc = 0; kc < 32; kc += 16) {
            u32 afh[4][4], afl[4][4], bfh[4][2], bfl[4][2];
#pragma unroll
            for (int mf = 0; mf < 4; mf++) {
                int r = wm * 64 + mf * 16 + ((lm & 1) << 3) + lrow;
                int cc2 = kc + ((lm & 2) << 2);
                u32 addr = stg2 + (u32)(r * 40 + cc2) * 2;
                ldmx4(afh[mf], addr);
                ldmx4(afl[mf], addr + 10240);
            }
#pragma unroll
            for (int np = 0; np < 2; np++) {
                int r = wn * 32 + np * 16 + ((lm & 2) << 2) + lrow;
                int cc2 = kc + ((lm & 1) << 3);
                u32 addr = stg2 + bofs + (u32)(r * 40 + cc2) * 2;
                u32 rr[4];
                ldmx4(rr, addr);
                bfh[np * 2][0] = rr[0]; bfh[np * 2][1] = rr[1];
                bfh[np * 2 + 1][0] = rr[2]; bfh[np * 2 + 1][1] = rr[3];
                ldmx4(rr, addr + dlo);
                bfl[np * 2][0] = rr[0]; bfl[np * 2][1] = rr[1];
                bfl[np * 2 + 1][0] = rr[2]; bfl[np * 2 + 1][1] = rr[3];
            }
#pragma unroll
            for (int mf = 0; mf < 4; mf++)
#pragma unroll
                for (int nf = 0; nf < 4; nf++) {
                    mma16816(acc[mf][nf], afh[mf], bfh[nf]);
                    mma16816(acc[mf][nf], afh[mf], bfl[nf]);
                    mma16816(acc[mf][nf], afl[mf], bfh[nf]);
                }
        }
        __syncthreads();
    }
#pragma unroll
    for (int mf = 0; mf < 4; mf++) {
        int rg = by * 128 + wm * 64 + mf * 16 + (lane >> 2);
#pragma unroll
        for (int nf = 0; nf < 4; nf++) {
            int cg = bx * 128 + wn * 32 + nf * 8 + (lane & 3) * 2;
            float* a = acc[mf][nf];
            float* p = C + (size_t)zout * CC * CC + (size_t)rg * CC + cg;
            *(float2*)p = make_float2(a[0], a[1]);
            *(float2*)(p + 8 * CC) = make_float2(a[2], a[3]);
        }
    }
}

// ---------------- stage C GEMM: M=256 rows per CTA, B via ldmatrix.trans ----
// out[c, n] = M[c,:]x[:,n] + cv[c] + x[c,n], B = y [d][n] layout.
#define ASZ_C 10240           // u16: Ah 256x40
#define BSZ_C 4352            // u16: Bh 32x136
#define STGU_C (2 * ASZ_C + 2 * BSZ_C)   // 29184 u16 per stage
__global__ void __launch_bounds__(256, 1) cgemm(
    const bf16* __restrict__ Ahg, const bf16* __restrict__ Alg,
    const bf16* __restrict__ Bhg, const bf16* __restrict__ Blg,
    const float* __restrict__ cvv, float* __restrict__ outp)
{
    extern __shared__ __align__(16) u16 smp[];
    int tid = threadIdx.x, lane = tid & 31, wid = tid >> 5;
    int wm = wid >> 2, wn = wid & 3;
    int bx = blockIdx.x, b = blockIdx.z;

    const bf16* Abh = Ahg + (size_t)b * CC * CC;
    const bf16* Abl = Alg + (size_t)b * CC * CC;
    const bf16* Bbh = Bhg + (size_t)b * CC * NPIX + bx * 128;
    const bf16* Bbl = Blg + (size_t)b * CC * NPIX + bx * 128;

    u32 sbase;
    asm("{ .reg .u64 t; cvta.to.shared.u64 t, %1; cvt.u32.u64 %0, t; }"
        : "=r"(sbase) : "l"(smp));

    auto PREF = [&](int t) {
        if (t < 8) {
            int k0 = t * 32, st = t & 1;
            u32 s0 = sbase + (u32)(st * STGU_C) * 2;
#pragma unroll
            for (int j = 0; j < 4; j++) {
                int idx = tid * 4 + j;
                int rA = idx >> 2, cA8 = (idx & 3) * 8;
                u32 offA = (u32)(rA * 40 + cA8) * 2;
                cp16(s0 + offA, Abh + (size_t)rA * CC + k0 + cA8);
                cp16(s0 + offA + (u32)ASZ_C * 2, Abl + (size_t)rA * CC + k0 + cA8);
            }
#pragma unroll
            for (int j = 0; j < 2; j++) {
                int idx = tid * 2 + j;
                int rB = idx >> 4, cB8 = (idx & 15) * 8;
                u32 offB = (u32)(2 * ASZ_C + rB * 136 + cB8) * 2;
                cp16(s0 + offB, Bbh + (size_t)(k0 + rB) * NPIX + cB8);
                cp16(s0 + offB + (u32)BSZ_C * 2, Bbl + (size_t)(k0 + rB) * NPIX + cB8);
            }
        }
        asm volatile("cp.async.commit_group;" ::: "memory");
    };

    float acc[8][4][4] = {};
    PREF(0);
    for (int t = 0; t < 8; t++) {
        PREF(t + 1);
        asm volatile("cp.async.wait_group 1;" ::: "memory");
        __syncthreads();
        int st = t & 1;
        u16 (*BhT)[136] = (u16(*)[136])(smp + st * STGU_C + 2 * ASZ_C);
        u16 (*BlT)[136] = (u16(*)[136])(smp + st * STGU_C + 2 * ASZ_C + BSZ_C);
        u32 stg2 = sbase + (u32)(st * STGU_C) * 2;
        int lrow = lane & 7, lm = lane >> 3;
#pragma unroll
        for (int kc = 0; kc < 32; kc += 16) {
            u32 bfh[4][2], bfl[4][2];
            {
                int jj = lane >> 3;
                int rrow = kc + (jj & 1) * 8 + (lane & 7);
                u32 base = stg2 + (u32)(2 * ASZ_C + rrow * 136) * 2;
                u32 a0 = base + (u32)(wn * 32 + (jj >> 1) * 8) * 2;
                u32 a1 = a0 + 32;
                u32 rb[8], rbl2[8];
                ldmx4t(rb + 0, a0);
                ldmx4t(rb + 4, a1);
                ldmx4t(rbl2 + 0, a0 + (u32)BSZ_C * 2);
                ldmx4t(rbl2 + 4, a1 + (u32)BSZ_C * 2);
#pragma unroll
                for (int nf = 0; nf < 4; nf++) {
                    bfh[nf][0] = rb[nf * 2];
                    bfh[nf][1] = rb[nf * 2 + 1];
                    bfl[nf][0] = rbl2[nf * 2];
                    bfl[nf][1] = rbl2[nf * 2 + 1];
                }
            }
#pragma unroll
            for (int mf = 0; mf < 8; mf++) {
                int r = wm * 128 + mf * 16 + ((lm & 1) << 3) + lrow;
                int cc2 = kc + ((lm & 2) << 2);
                u32 addr = stg2 + (u32)(r * 40 + cc2) * 2;
                u32 afh[4], afl[4];
                ldmx4(afh, addr);
                ldmx4(afl, addr + (u32)ASZ_C * 2);
#pragma unroll
                for (int nf = 0; nf < 4; nf++) {
                    mma16816(acc[mf][nf], afh, bfh[nf]);
                    mma16816(acc[mf][nf], afh, bfl[nf]);
                    mma16816(acc[mf][nf], afl, bfh[nf]);
                }
            }
        }
        {
            int tb = wm * 4;
#pragma unroll
            for (int mf = 0; mf < 8; mf++) {
                if (t == tb + (mf >> 1)) {
                    int row = (mf & 1) * 16 + (lane >> 2);
#pragma unroll
                    for (int nf = 0; nf < 4; nf++) {
                        int cl = wn * 32 + nf * 8 + (lane & 3) * 2;
                        acc[mf][nf][0] += b2f(BhT[row][cl]) + b2f(BlT[row][cl]);
                        acc[mf][nf][1] += b2f(BhT[row][cl + 1]) + b2f(BlT[row][cl + 1]);
                        acc[mf][nf][2] += b2f(BhT[row + 8][cl]) + b2f(BlT[row + 8][cl]);
                        acc[mf][nf][3] += b2f(BhT[row + 8][cl + 1]) + b2f(BlT[row + 8][cl + 1]);
                    }
                }
            }
        }
        __syncthreads();
    }

#pragma unroll
    for (int mf = 0; mf < 8; mf++) {
        int rg = wm * 128 + mf * 16 + (lane >> 2);
        float cv0 = cvv[b * CC + rg];
        float cv1 = cvv[b * CC + rg + 8];
#pragma unroll
        for (int nf = 0; nf < 4; nf++) {
            int cg = bx * 128 + wn * 32 + nf * 8 + (lane & 3) * 2;
            float* a = acc[mf][nf];
            size_t o0 = (size_t)b * CC * NPIX + (size_t)rg * NPIX + cg;
            size_t o1 = o0 + 8 * NPIX;
            *(float2*)(outp + o0) = make_float2(a[0] + cv0, a[1] + cv0);
            *(float2*)(outp + o1) = make_float2(a[2] + cv1, a[3] + cv1);
        }
    }
}

// ---------------- fp32-input hi/lo mma GEMM (small GEMMs; proven) -----------
template <int EPI>
__global__ void __launch_bounds__(256, 1) mgemm(
    const float* __restrict__ A, const float* __restrict__ B, float* __restrict__ C,
    int K, int lda, int ldb, long sA, long sB, long sC)
{
    __shared__ __align__(16) u16 Ah[128][40], Al[128][40];
    __shared__ __align__(16) u16 Bh[128][40], Bl[128][40];
    int tid = threadIdx.x, lane = tid & 31, wid = tid >> 5;
    int wm = wid >> 2, wn = wid & 3;
    int bx = blockIdx.x, by = blockIdx.y, b = blockIdx.z;
    const float* Ab = A + (size_t)b * sA + (size_t)(by * 128) * lda;
    const float* Bb = B + (size_t)b * sB;
    float acc[4][4][4] = {};
    float4 va[4], vb[4];
    int arow = tid >> 1, acb = (tid & 1) * 16;
    auto LDG = [&](int k0) {
#pragma unroll
        for (int j = 0; j < 4; j++) {
            va[j] = *(const float4*)(Ab + (size_t)arow * lda + k0 + acb + 4 * j);
            vb[j] = *(const float4*)(Bb + (size_t)(bx * 128 + arow) * ldb + k0 + acb + 4 * j);
        }
    };
    auto STS = [&]() {
#pragma unroll
        for (int j = 0; j < 4; j++) {
            uint2 h, l;
            cvt4(va[j], h, l);
            *(uint2*)&Ah[arow][acb + 4 * j] = h;
            *(uint2*)&Al[arow][acb + 4 * j] = l;
            cvt4(vb[j], h, l);
            *(uint2*)&Bh[arow][acb + 4 * j] = h;
            *(uint2*)&Bl[arow][acb + 4 * j] = l;
        }
    };
    int T = K >> 5;
    LDG(0);
    for (int t = 0; t < T; t++) {
        STS();
        __syncthreads();
        if (t + 1 < T) LDG((t + 1) << 5);
#pragma unroll
        for (int kc = 0; kc < 32; kc += 16) {
            int kk = kc + (lane & 3) * 2;
            u32 afh[4][4], afl[4][4], bfh[4][2], bfl[4][2];
#pragma unroll
            for (int mf = 0; mf < 4; mf++) {
                int r0 = wm * 64 + mf * 16 + (lane >> 2);
                afh[mf][0] = *(const u32*)&Ah[r0][kk];
                afh[mf][1] = *(const u32*)&Ah[r0 + 8][kk];
                afh[mf][2] = *(const u32*)&Ah[r0][kk + 8];
                afh[mf][3] = *(const u32*)&Ah[r0 + 8][kk + 8];
                afl[mf][0] = *(const u32*)&Al[r0][kk];
                afl[mf][1] = *(const u32*)&Al[r0 + 8][kk];
                afl[mf][2] = *(const u32*)&Al[r0][kk + 8];
                afl[mf][3] = *(const u32*)&Al[r0 + 8][kk + 8];
            }
#pragma unroll
            for (int nf = 0; nf < 4; nf++) {
                int c0 = wn * 32 + nf * 8 + (lane >> 2);
                bfh[nf][0] = *(const u32*)&Bh[c0][kk];
                bfh[nf][1] = *(const u32*)&Bh[c0][kk + 8];
                bfl[nf][0] = *(const u32*)&Bl[c0][kk];
                bfl[nf][1] = *(const u32*)&Bl[c0][kk + 8];
            }
#pragma unroll
            for (int mf = 0; mf < 4; mf++)
#pragma unroll
                for (int nf = 0; nf < 4; nf++) {
                    mma16816(acc[mf][nf], afh[mf], bfh[nf]);
                    mma16816(acc[mf][nf], afh[mf], bfl[nf]);
                    mma16816(acc[mf][nf], afl[mf], bfh[nf]);
                }
        }
        __syncthreads();
    }
#pragma unroll
    for (int mf = 0; mf < 4; mf++) {
        int rg = by * 128 + wm * 64 + mf * 16 + (lane >> 2);
#pragma unroll
        for (int nf = 0; nf < 4; nf++) {
            int cg = bx * 128 + wn * 32 + nf * 8 + (lane & 3) * 2;
            float* a = acc[mf][nf];
            if (EPI == 0) {
                float* p = C + (size_t)b * sC + (size_t)rg * CC + cg;
                *(float2*)p = make_float2(a[0], a[1]);
                *(float2*)(p + 8 * CC) = make_float2(a[2], a[3]);
            } else {
                size_t i0 = (size_t)b * CC * CC + (size_t)rg * CC + cg;
                size_t i1 = i0 + 8 * CC;
                bf16 h0, l0, h1, l1;
                split2(a[0], h0, l0); split2(a[1], h1, l1);
                *(u32*)&g_Mh[i0] = pack2(h0, h1);
                *(u32*)&g_Ml[i0] = pack2(l0, l1);
                split2(a[2], h0, l0); split2(a[3], h1, l1);
                *(u32*)&g_Mh[i1] = pack2(h0, h1);
                *(u32*)&g_Ml[i1] = pack2(l0, l1);
            }
        }
    }
}

// ---------------- split x -> yh/yl and row-sum partials (8 elem/thread) -----
__global__ void splitx_kernel(const float* __restrict__ x) {
    int b = blockIdx.z, c0 = blockIdx.y * 32, n0 = blockIdx.x * 64;
    int tid = threadIdx.x;
    int c = tid >> 3, n8 = (tid & 7) * 8;
    const float* src = x + ((size_t)(b * CC + c0 + c)) * NPIX + n0 + n8;
    float4 v0 = *(const float4*)src;
    float4 v1 = *(const float4*)(src + 4);
    uint2 h0, l0, h1, l1;
    cvt4(v0, h0, l0);
    cvt4(v1, h1, l1);
    size_t yo = ((size_t)(b * CC + c0 + c)) * NPIX + n0 + n8;
    *(uint4*)(g_yh + yo) = make_uint4(h0.x, h0.y, h1.x, h1.y);
    *(uint4*)(g_yl + yo) = make_uint4(l0.x, l0.y, l1.x, l1.y);
    float ps = ((v0.x + v0.y) + (v0.z + v0.w)) + ((v1.x + v1.y) + (v1.z + v1.w));
#pragma unroll
    for (int o = 4; o; o >>= 1) ps += __shfl_down_sync(0xFFFFFFFFu, ps, o, 8);
    if ((tid & 7) == 0)
        g_sxp[(size_t)(b * CC + c0 + c) * 64 + blockIdx.x] = ps;
}

// ---------------- reduce row-sum partials: warp per row ---------------------
__global__ void reduce_sx_kernel() {
    int row = blockIdx.x * 8 + (threadIdx.x >> 5);
    int lane = threadIdx.x & 31;
    const float* p = g_sxp + (size_t)row * 64;
    float s = p[lane] + p[lane + 32];
#pragma unroll
    for (int o = 16; o; o >>= 1) s += __shfl_down_sync(0xFFFFFFFFu, s, o);
    if (lane == 0) g_sx[row] = s;
}

// ---------------- qs/ks: warp per output, grid-parallel ---------------------
__global__ void proj_sums(const float* __restrict__ wq, const float* __restrict__ wk) {
    __shared__ float sxs[CC];
    int b = blockIdx.x, mat = blockIdx.y, zc = blockIdx.z;
    int tid = threadIdx.x, lane = tid & 31, wid = tid >> 5;
    sxs[tid] = g_sx[b * CC + tid];
    __syncthreads();
    const float* w = mat ? wk : wq;
    float* outv = mat ? g_ks : g_qs;
#pragma unroll
    for (int i = 0; i < 4; i++) {
        int o = zc * 32 + wid * 4 + i;
        const float* r = w + o * CC;
        float s = 0.f;
#pragma unroll
        for (int j = 0; j < 8; j++) {
            int cidx = lane + 32 * j;
            s += r[cidx] * sxs[cidx];
        }
#pragma unroll
        for (int off = 16; off; off >>= 1) s += __shfl_down_sync(0xFFFFFFFFu, s, off);
        if (lane == 0) outv[b * CC + o] = s;
    }
}

// ---------------- softmax (+ folded cv = A bv), warp-shuffle ----------------
__global__ void softmax_kernel(const float* __restrict__ bq, const float* __restrict__ bk,
                               const float* __restrict__ bv) {
    int row = blockIdx.x;
    int b = row >> 8, c = row & 255;
    int d = threadIdx.x, lane = d & 31, wid = d >> 5;
    __shared__ float sm[8], sm2[8], sm3[8];
    float v = g_L[(size_t)row * CC + d];
    float bqc = bq[c];
    v += g_qs[b * CC + c] * bk[d] + bqc * g_ks[b * CC + d] + 4096.f * bqc * bk[d];
    v *= 0.0625f;
    float wmx = v;
#pragma unroll
    for (int o = 16; o; o >>= 1) wmx = fmaxf(wmx, __shfl_xor_sync(0xFFFFFFFFu, wmx, o));
    if (lane == 0) sm[wid] = wmx;
    __syncthreads();
    float m = sm[0];
#pragma unroll
    for (int i = 1; i < 8; i++) m = fmaxf(m, sm[i]);
    float e = __expf(v - m);
    float ws = e;
#pragma unroll
    for (int o = 16; o; o >>= 1) ws += __shfl_xor_sync(0xFFFFFFFFu, ws, o);
    if (lane == 0) sm2[wid] = ws;
    __syncthreads();
    float s = sm2[0];
#pragma unroll
    for (int i = 1; i < 8; i++) s += sm2[i];
    float p = e * (1.0f / s);
    g_L[(size_t)row * CC + d] = p;
    float cvp = p * bv[d];
#pragma unroll
    for (int o = 16; o; o >>= 1) cvp += __shfl_xor_sync(0xFFFFFFFFu, cvp, o);
    if (lane == 0) sm3[wid] = cvp;
    __syncthreads();
    if (d == 0) {
        float cs = sm3[0];
#pragma unroll
        for (int i = 1; i < 8; i++) cs += sm3[i];
        g_cv[row] = cs;
    }
}

// ---------------- misc small kernels ----------------------------------------
__global__ void wvt_kernel(const float* __restrict__ wv) {
    int d = blockIdx.x, e = threadIdx.x;
    g_Wvt[e * CC + d] = wv[d * CC + e];
}
__global__ void reduceg_kernel() {
    int i = (blockIdx.x * 256 + threadIdx.x) * 4;
    float4 a = *(const float4*)(g_Gp + i);
    float4 b = *(const float4*)(g_Gp + (size_t)BB * CC * CC + i);
    float4 c = *(const float4*)(g_Gp + (size_t)2 * BB * CC * CC + i);
    *(float4*)(g_G + i) = make_float4(a.x + b.x + c.x, a.y + b.y + c.y,
                                      a.z + b.z + c.z, a.w + b.w + c.w);
}
__global__ void mirror_kernel() {
    __shared__ float s[32][33];
    int b = blockIdx.z;
    int r0 = 128 + blockIdx.y * 32;
    int c0 = blockIdx.x * 32;
    float* Gb = g_G + (size_t)b * CC * CC;
    int tx = threadIdx.x & 31, ty = threadIdx.x >> 5;
#pragma unroll
    for (int i = ty; i < 32; i += 8)
        s[i][tx] = Gb[(size_t)(r0 + i) * CC + c0 + tx];
    __syncthreads();
#pragma unroll
    for (int i = ty; i < 32; i += 8)
        Gb[(size_t)(c0 + i) * CC + r0 + tx] = s[tx][i];
}

// ---------------- launcher ----------------
extern "C" void kernel_launch(void* const* d_in, const int* in_sizes, int n_in,
                              void* d_out, int out_size) {
    const float* x  = (const float*)d_in[0];
    const float* wq = (const float*)d_in[1];
    const float* bq = (const float*)d_in[2];
    const float* wk = (const float*)d_in[3];
    const float* bk = (const float*)d_in[4];
    const float* wv = (const float*)d_in[5];
    const float* bv = (const float*)d_in[6];
    float* out = (float*)d_out;

    float *pG, *pGp, *pT, *pL, *pWvt, *pcv;
    bf16 *pyh, *pyl, *pMh, *pMl;
    cudaGetSymbolAddress((void**)&pG, g_G);
    cudaGetSymbolAddress((void**)&pGp, g_Gp);
    cudaGetSymbolAddress((void**)&pT, g_T);
    cudaGetSymbolAddress((void**)&pL, g_L);
    cudaGetSymbolAddress((void**)&pWvt, g_Wvt);
    cudaGetSymbolAddress((void**)&pcv, g_cv);
    cudaGetSymbolAddress((void**)&pyh, g_yh);
    cudaGetSymbolAddress((void**)&pyl, g_yl);
    cudaGetSymbolAddress((void**)&pMh, g_Mh);
    cudaGetSymbolAddress((void**)&pMl, g_Ml);

    const int SMEMG = 2 * STGU_G * 2;   // 81920 B
    const int SMEMC = 2 * STGU_C * 2;   // 116736 B
    cudaFuncSetAttribute((const void*)ggemm, cudaFuncAttributeMaxDynamicSharedMemorySize, SMEMG);
    cudaFuncSetAttribute((const void*)cgemm, cudaFuncAttributeMaxDynamicSharedMemorySize, SMEMC);

    const long C2 = (long)CC * CC;

    splitx_kernel<<<dim3(64, 8, 16), 256>>>(x);
    reduce_sx_kernel<<<512, 256>>>();
    wvt_kernel<<<256, 256>>>(wv);
    proj_sums<<<dim3(16, 2, 8), 256>>>(wq, wk);
    // G partials: y y^T bf16, symmetric triangle tiles x split-K 3
    ggemm<<<dim3(3, 3, 16), 256, SMEMG>>>(pyh, pyl, pGp);
    reduceg_kernel<<<1024, 256>>>();
    mirror_kernel<<<dim3(4, 4, 16), 256>>>();
    // T = Wq G ; L = T Wk^T ; softmax(+cv) ; M = A Wv^T (bf16 epilogue)
    mgemm<0><<<dim3(2, 2, 16), 256>>>(wq, pG, pT, CC, CC, CC, 0, C2, C2);
    mgemm<0><<<dim3(2, 2, 16), 256>>>(pT, wk, pL, CC, CC, CC, C2, 0, C2);
    softmax_kernel<<<4096, 256>>>(bq, bk, bv);
    mgemm<1><<<dim3(2, 2, 16), 256>>>(pL, pWvt, nullptr, CC, CC, CC, C2, 0, 0);
    // out = x + M x + cv  (M=256 rows per CTA)
    cgemm<<<dim3(32, 1, 16), 256, SMEMC>>>(pMh, pMl, pyh, pyl, pcv, out);
}